// round 17
// baseline (speedup 1.0000x reference)
#include <cuda_runtime.h>
#include <cuda_bf16.h>
#include <math.h>
#include <stdint.h>

// Problem constants
#define T_STEPS 512
#define BATCH   128
#define DIN     256
#define HID     256
#define NCOLS   2048            // dir*1024 + gate*256 + j
#define OUT_TB_STRIDE 512
#define OUT_MAIN (T_STEPS*BATCH*OUT_TB_STRIDE)

#define GEMM_BLKS_PER_T 16      // 16 mtiles of 128 ncols each
#define GRP_ARRIVE 8            // j-octant CTAs per (dir, batch-half)

// xg scratch, layout [t][ncol(2048)][b(128)] fp32 (536 MB)
__device__ float g_xg[(size_t)T_STEPS * NCOLS * BATCH];
// bf16 hi/lo planes of X ([t*128+b][k]) and Wcat ([ncol][k])
__device__ __nv_bfloat16 g_xhi[(size_t)T_STEPS * BATCH * DIN];
__device__ __nv_bfloat16 g_xlo[(size_t)T_STEPS * BATCH * DIN];
__device__ __nv_bfloat16 g_whi[NCOLS * DIN];
__device__ __nv_bfloat16 g_wlo[NCOLS * DIN];
__device__ float g_bias[NCOLS];
// h ping-pong per (dir, batch-half): [dir][bg][buf][hilo][lb(64)][k(256)]
__device__ __nv_bfloat16 g_hbf[2][2][2][2][64][HID];
// sync counters
__device__ int g_bar[2][2][T_STEPS];   // fan-in 8 per (dir,bg)
__device__ int g_xg_ready[T_STEPS];

__device__ __forceinline__ float sigm(float x) { return 1.f / (1.f + expf(-x)); }

// mma.sync m16n8k16 row.col f32.bf16.bf16.f32  (baseline PTX, sm_80+)
__device__ __forceinline__ void mma_bf16(float* d, const uint32_t* a, const uint32_t* b) {
    asm volatile(
        "mma.sync.aligned.m16n8k16.row.col.f32.bf16.bf16.f32 "
        "{%0,%1,%2,%3}, {%4,%5,%6,%7}, {%8,%9}, {%0,%1,%2,%3};"
        : "+f"(d[0]), "+f"(d[1]), "+f"(d[2]), "+f"(d[3])
        : "r"(a[0]), "r"(a[1]), "r"(a[2]), "r"(a[3]), "r"(b[0]), "r"(b[1]));
}

// ---------------------------------------------------------------------------
// init kernels: hi/lo splits + counters + h0 conversion
// ---------------------------------------------------------------------------
__global__ void split_w_kernel(
    const float* __restrict__ Wf, const float* __restrict__ Wb,
    const float* __restrict__ bif, const float* __restrict__ bhf,
    const float* __restrict__ bib, const float* __restrict__ bhb)
{
    int idx = blockIdx.x * 256 + threadIdx.x;     // 0..524287
    int row = idx >> 8, k = idx & 255;
    int dir = row >> 10, r = row & 1023;
    float v = (dir ? Wb : Wf)[r * DIN + k];
    __nv_bfloat16 hi = __float2bfloat16(v);
    g_whi[idx] = hi;
    g_wlo[idx] = __float2bfloat16(v - __bfloat162float(hi));
    if (idx < NCOLS) {
        int d2 = idx >> 10, r2 = idx & 1023;
        g_bias[idx] = (d2 ? bib[r2] : bif[r2]) + (d2 ? bhb[r2] : bhf[r2]);
    }
}

__global__ void split_x_kernel(const float* __restrict__ X)
{
    size_t i = ((size_t)blockIdx.x * 256 + threadIdx.x) * 8;   // 8192 blocks
    float4 a = *(const float4*)(X + i);
    float4 b = *(const float4*)(X + i + 4);
    __nv_bfloat16 hi[8], lo[8];
    float v[8] = {a.x,a.y,a.z,a.w,b.x,b.y,b.z,b.w};
    #pragma unroll
    for (int c = 0; c < 8; c++) {
        hi[c] = __float2bfloat16(v[c]);
        lo[c] = __float2bfloat16(v[c] - __bfloat162float(hi[c]));
    }
    *(uint4*)(g_xhi + i) = *(uint4*)hi;
    *(uint4*)(g_xlo + i) = *(uint4*)lo;
}

__global__ void init_misc_kernel(const float* __restrict__ h0)
{
    int i = blockIdx.x * 256 + threadIdx.x;   // 0..65535 (grid 256)
    int dir = i >> 15;
    int rem = i & 32767;                       // b*HID + k
    int b = rem >> 8, k = rem & 255;
    int bg = b >> 6, lb = b & 63;
    float h = h0[i];
    __nv_bfloat16 hh = __float2bfloat16(h);
    __nv_bfloat16 hl = __float2bfloat16(h - __bfloat162float(hh));
    g_hbf[dir][bg][1][0][lb][k] = hh;          // step 0 reads buf (0+1)&1 = 1
    g_hbf[dir][bg][1][1][lb][k] = hl;
    if (i < 2 * 2 * T_STEPS) ((int*)g_bar)[i] = 0;
    if (i < T_STEPS) g_xg_ready[i] = 0;
}

// ---------------------------------------------------------------------------
// Phase 1 HMMA gemm: xg[t][ncol][b] = Wcat @ X[t]^T + bias  (bf16x3).
// grid (16 mtile, 512 bm->t both-ends), 512 threads = 16 warps (4m x 4n).
// ---------------------------------------------------------------------------
#define GS_STRIDE 72
#define GEMM_SMEM (4 * 128 * GS_STRIDE * 2)     // 73,728 B

__global__ __launch_bounds__(512) void gemm_hmma_kernel()
{
    extern __shared__ __nv_bfloat16 gsm[];
    __nv_bfloat16* As_hi = gsm;
    __nv_bfloat16* As_lo = gsm + 128 * GS_STRIDE;
    __nv_bfloat16* Bs_hi = gsm + 2 * 128 * GS_STRIDE;
    __nv_bfloat16* Bs_lo = gsm + 3 * 128 * GS_STRIDE;

    const int mtile = blockIdx.x;           // 0..15
    const int bm    = blockIdx.y;           // 0..511
    const int t     = (bm & 1) ? (T_STEPS - 1 - (bm >> 1)) : (bm >> 1);
    const int tid   = threadIdx.x;
    const int warp  = tid >> 5;
    const int wm    = warp >> 2;            // 0..3
    const int wn    = warp & 3;             // 0..3
    const int ln    = tid & 31;
    const int grp   = ln >> 2;
    const int tig   = ln & 3;

    const int ldRow = tid >> 2;             // 0..127
    const int ldSeg = tid & 3;              // 0..3 (16 bf16 each)

    float acc[2][4][4];
    #pragma unroll
    for (int mt = 0; mt < 2; mt++)
        #pragma unroll
        for (int nt = 0; nt < 4; nt++)
            #pragma unroll
            for (int c = 0; c < 4; c++) acc[mt][nt][c] = 0.f;

    const size_t wbase = (size_t)(mtile * 128) * DIN;
    const size_t xbase = (size_t)t * BATCH * DIN;

    for (int kc = 0; kc < 4; kc++) {
        const int koff = kc * 64 + ldSeg * 16;
        {
            uint4 a0 = *(const uint4*)(g_whi + wbase + (size_t)ldRow * DIN + koff);
            uint4 a1 = *(const uint4*)(g_whi + wbase + (size_t)ldRow * DIN + koff + 8);
            uint4 a2 = *(const uint4*)(g_wlo + wbase + (size_t)ldRow * DIN + koff);
            uint4 a3 = *(const uint4*)(g_wlo + wbase + (size_t)ldRow * DIN + koff + 8);
            uint4 b0 = *(const uint4*)(g_xhi + xbase + (size_t)ldRow * DIN + koff);
            uint4 b1 = *(const uint4*)(g_xhi + xbase + (size_t)ldRow * DIN + koff + 8);
            uint4 b2 = *(const uint4*)(g_xlo + xbase + (size_t)ldRow * DIN + koff);
            uint4 b3 = *(const uint4*)(g_xlo + xbase + (size_t)ldRow * DIN + koff + 8);
            *(uint4*)&As_hi[ldRow * GS_STRIDE + ldSeg * 16]     = a0;
            *(uint4*)&As_hi[ldRow * GS_STRIDE + ldSeg * 16 + 8] = a1;
            *(uint4*)&As_lo[ldRow * GS_STRIDE + ldSeg * 16]     = a2;
            *(uint4*)&As_lo[ldRow * GS_STRIDE + ldSeg * 16 + 8] = a3;
            *(uint4*)&Bs_hi[ldRow * GS_STRIDE + ldSeg * 16]     = b0;
            *(uint4*)&Bs_hi[ldRow * GS_STRIDE + ldSeg * 16 + 8] = b1;
            *(uint4*)&Bs_lo[ldRow * GS_STRIDE + ldSeg * 16]     = b2;
            *(uint4*)&Bs_lo[ldRow * GS_STRIDE + ldSeg * 16 + 8] = b3;
        }
        __syncthreads();

        #pragma unroll
        for (int kt = 0; kt < 4; kt++) {
            const int k0 = kt * 16 + tig * 2;
            uint32_t Ah[2][4], Al[2][4], Bh[4][2], Bl[4][2];
            #pragma unroll
            for (int mt = 0; mt < 2; mt++) {
                int m = wm * 32 + mt * 16 + grp;
                Ah[mt][0] = *(const uint32_t*)&As_hi[(m    ) * GS_STRIDE + k0];
                Ah[mt][1] = *(const uint32_t*)&As_hi[(m + 8) * GS_STRIDE + k0];
                Ah[mt][2] = *(const uint32_t*)&As_hi[(m    ) * GS_STRIDE + k0 + 8];
                Ah[mt][3] = *(const uint32_t*)&As_hi[(m + 8) * GS_STRIDE + k0 + 8];
                Al[mt][0] = *(const uint32_t*)&As_lo[(m    ) * GS_STRIDE + k0];
                Al[mt][1] = *(const uint32_t*)&As_lo[(m + 8) * GS_STRIDE + k0];
                Al[mt][2] = *(const uint32_t*)&As_lo[(m    ) * GS_STRIDE + k0 + 8];
                Al[mt][3] = *(const uint32_t*)&As_lo[(m + 8) * GS_STRIDE + k0 + 8];
            }
            #pragma unroll
            for (int nt = 0; nt < 4; nt++) {
                int n = wn * 32 + nt * 8 + grp;
                Bh[nt][0] = *(const uint32_t*)&Bs_hi[n * GS_STRIDE + k0];
                Bh[nt][1] = *(const uint32_t*)&Bs_hi[n * GS_STRIDE + k0 + 8];
                Bl[nt][0] = *(const uint32_t*)&Bs_lo[n * GS_STRIDE + k0];
                Bl[nt][1] = *(const uint32_t*)&Bs_lo[n * GS_STRIDE + k0 + 8];
            }
            #pragma unroll
            for (int mt = 0; mt < 2; mt++)
                #pragma unroll
                for (int nt = 0; nt < 4; nt++) {
                    mma_bf16(acc[mt][nt], Ah[mt], Bh[nt]);
                    mma_bf16(acc[mt][nt], Al[mt], Bh[nt]);
                    mma_bf16(acc[mt][nt], Ah[mt], Bl[nt]);
                }
        }
        __syncthreads();
    }

    // epilogue: + bias[m], store float2 along b
    #pragma unroll
    for (int mt = 0; mt < 2; mt++)
        #pragma unroll
        for (int rr = 0; rr < 2; rr++) {
            int m_local = wm * 32 + mt * 16 + grp + rr * 8;
            float bv = g_bias[mtile * 128 + m_local];
            size_t rowbase = ((size_t)t * NCOLS + mtile * 128 + m_local) * BATCH;
            #pragma unroll
            for (int nt = 0; nt < 4; nt++) {
                int b = wn * 32 + nt * 8 + tig * 2;
                *(float2*)(g_xg + rowbase + b) =
                    make_float2(acc[mt][nt][rr * 2] + bv, acc[mt][nt][rr * 2 + 1] + bv);
            }
        }

    __threadfence();
    __syncthreads();
    if (tid == 0) atomicAdd(&g_xg_ready[t], 1);
}

// ---------------------------------------------------------------------------
// Persistent HMMA recurrence, batch-partitioned sync groups.
// grid = 32 CTAs: dir = blk>>4, bg = (blk>>3)&1 (batch half),
//                 jq = blk&7 (owns j in [jq*32, jq*32+32)).
// 256 threads = 8 warps: wm = warp>>2 (batch 32-half of the 64),
//                        wn = warp&3 (j 8-slice of the 32).
// Per-CTA GEMM: M=64 (batches), N=128 (4 gates x 32 j, row n = gate*32+jj),
// K=256, bf16x3. Warp tile M=32 x N=32 (nt = gate), acc[2][4][4].
// Sync: fan-in 8 within (dir,bg); h buffers 64 batches only.
// ---------------------------------------------------------------------------
#define HS_STRIDE 264
#define WS_ROWS 128
#define HS_ROWS 64
#define WS_ELEMS (WS_ROWS * HS_STRIDE)
#define HS_ELEMS (HS_ROWS * HS_STRIDE)
#define SMEM_TOTAL ((2 * WS_ELEMS + 2 * HS_ELEMS) * 2)   // 202,752 B

extern "C" __global__ void __launch_bounds__(256) lstm_mma_kernel(
    const float* __restrict__ Whh_f, const float* __restrict__ Whh_b,
    const float* __restrict__ c0, float* __restrict__ out)
{
    extern __shared__ __nv_bfloat16 smem[];
    __nv_bfloat16* ws_hi = smem;
    __nv_bfloat16* ws_lo = smem + WS_ELEMS;
    __nv_bfloat16* hs_hi = smem + 2 * WS_ELEMS;
    __nv_bfloat16* hs_lo = smem + 2 * WS_ELEMS + HS_ELEMS;

    const int blk = blockIdx.x;
    const int dir = blk >> 4;
    const int bg  = (blk >> 3) & 1;
    const int jq  = blk & 7;
    const int tid = threadIdx.x;
    const int warp = tid >> 5;
    const int wm  = warp >> 2;              // 0..1
    const int wn  = warp & 3;               // 0..3
    const int ln  = tid & 31;
    const int grp = ln >> 2;
    const int tig = ln & 3;

    const float* Whh = dir ? Whh_b : Whh_f;

    // W slice: 128 rows, n = gate*32 + jj -> wrow = gate*256 + jq*32 + jj
    for (int i = tid; i < WS_ROWS * HID; i += 256) {
        int n = i >> 8, k = i & 255;
        int wrow = (n >> 5) * HID + jq * 32 + (n & 31);
        float wv = Whh[(size_t)wrow * HID + k];
        __nv_bfloat16 wh = __float2bfloat16(wv);
        ws_hi[n * HS_STRIDE + k] = wh;
        ws_lo[n * HS_STRIDE + k] = __float2bfloat16(wv - __bfloat162float(wh));
    }

    // cell state: 8 cells = (2 mt)(2 rr)(2 jb); lb = local batch (0..63)
    float cr[8];
    #pragma unroll
    for (int mt = 0; mt < 2; mt++)
        #pragma unroll
        for (int rr = 0; rr < 2; rr++)
            #pragma unroll
            for (int jb = 0; jb < 2; jb++) {
                int lb = wm * 32 + mt * 16 + grp + rr * 8;
                int gb = bg * 64 + lb;
                int j = jq * 32 + wn * 8 + tig * 2 + jb;
                cr[mt * 4 + rr * 2 + jb] =
                    c0[(size_t)dir * BATCH * HID + (size_t)gb * HID + j];
            }

    __syncthreads();

    for (int s = 0; s < T_STEPS; s++) {
        const int t = dir ? (T_STEPS - 1 - s) : s;

        // ---- wait: xg[t] produced ----
        if (tid == 0) {
            volatile int* px = &g_xg_ready[t];
            while (*px < GEMM_BLKS_PER_T) __nanosleep(64);
        }
        __syncthreads();

        // ---- prefetch xg into accumulators (overlaps the group barrier) ----
        float acc[2][4][4];
        #pragma unroll
        for (int mt = 0; mt < 2; mt++)
            #pragma unroll
            for (int nt = 0; nt < 4; nt++)
                #pragma unroll
                for (int rr = 0; rr < 2; rr++)
                    #pragma unroll
                    for (int jb = 0; jb < 2; jb++) {
                        int gb = bg * 64 + wm * 32 + mt * 16 + grp + rr * 8;
                        int ncol = dir * 1024 + nt * 256
                                 + jq * 32 + wn * 8 + tig * 2 + jb;
                        acc[mt][nt][rr * 2 + jb] =
                            __ldcg(g_xg + ((size_t)t * NCOLS + ncol) * BATCH + gb);
                    }

        // ---- wait: the 8 group CTAs finished step s-1 ----
        if (s > 0) {
            if (tid == 0) {
                volatile int* p = &g_bar[dir][bg][s - 1];
                while (*p < GRP_ARRIVE) __nanosleep(32);
            }
        }
        __syncthreads();

        // ---- stage group h planes [64 x 256] into padded SMEM ----
        {
            const uint4* src_hi = (const uint4*)&g_hbf[dir][bg][(s + 1) & 1][0][0][0];
            const uint4* src_lo = (const uint4*)&g_hbf[dir][bg][(s + 1) & 1][1][0][0];
            #pragma unroll
            for (int i = tid; i < 2048; i += 256) {     // uint4 = 8 bf16
                int lb = i >> 5, kq = i & 31;
                uint4 vh = __ldcv(src_hi + i);
                uint4 vl = __ldcv(src_lo + i);
                *(uint4*)&hs_hi[lb * HS_STRIDE + kq * 8] = vh;
                *(uint4*)&hs_lo[lb * HS_STRIDE + kq * 8] = vl;
            }
        }
        __syncthreads();

        // ---- K loop: 16 k-tiles x (2 mt x 4 nt=gate) x 3 passes ----
        #pragma unroll 4
        for (int kt = 0; kt < 16; kt++) {
            const int k0 = kt * 16 + tig * 2;
            uint32_t Ah[2][4], Al[2][4], Bh[4][2], Bl[4][2];
            #pragma unroll
            for (int mt = 0; mt < 2; mt++) {
                int lb = wm * 32 + mt * 16 + grp;
                Ah[mt][0] = *(const uint32_t*)&hs_hi[(lb    ) * HS_STRIDE + k0];
                Ah[mt][1] = *(const uint32_t*)&hs_hi[(lb + 8) * HS_STRIDE + k0];
                Ah[mt][2] = *(const uint32_t*)&hs_hi[(lb    ) * HS_STRIDE + k0 + 8];
                Ah[mt][3] = *(const uint32_t*)&hs_hi[(lb + 8) * HS_STRIDE + k0 + 8];
                Al[mt][0] = *(const uint32_t*)&hs_lo[(lb    ) * HS_STRIDE + k0];
                Al[mt][1] = *(const uint32_t*)&hs_lo[(lb + 8) * HS_STRIDE + k0];
                Al[mt][2] = *(const uint32_t*)&hs_lo[(lb    ) * HS_STRIDE + k0 + 8];
                Al[mt][3] = *(const uint32_t*)&hs_lo[(lb + 8) * HS_STRIDE + k0 + 8];
            }
            #pragma unroll
            for (int nt = 0; nt < 4; nt++) {
                int n = nt * 32 + wn * 8 + grp;
                Bh[nt][0] = *(const uint32_t*)&ws_hi[n * HS_STRIDE + k0];
                Bh[nt][1] = *(const uint32_t*)&ws_hi[n * HS_STRIDE + k0 + 8];
                Bl[nt][0] = *(const uint32_t*)&ws_lo[n * HS_STRIDE + k0];
                Bl[nt][1] = *(const uint32_t*)&ws_lo[n * HS_STRIDE + k0 + 8];
            }
            #pragma unroll
            for (int mt = 0; mt < 2; mt++)
                #pragma unroll
                for (int nt = 0; nt < 4; nt++) {
                    mma_bf16(acc[mt][nt], Ah[mt], Bh[nt]);
                    mma_bf16(acc[mt][nt], Al[mt], Bh[nt]);
                    mma_bf16(acc[mt][nt], Ah[mt], Bl[nt]);
                }
        }

        // ---- gates + c/h update; publish h FIRST (critical path) ----
        float hn[8], cn[8];
        __nv_bfloat16* hb_hi = &g_hbf[dir][bg][s & 1][0][0][0];
        __nv_bfloat16* hb_lo = &g_hbf[dir][bg][s & 1][1][0][0];
        #pragma unroll
        for (int mt = 0; mt < 2; mt++)
            #pragma unroll
            for (int rr = 0; rr < 2; rr++)
                #pragma unroll
                for (int jb = 0; jb < 2; jb++) {
                    int lb = wm * 32 + mt * 16 + grp + rr * 8;
                    int j = jq * 32 + wn * 8 + tig * 2 + jb;
                    int ci = mt * 4 + rr * 2 + jb;
                    int di = rr * 2 + jb;
                    float Gi = acc[mt][0][di];
                    float Gf = acc[mt][1][di];
                    float Gg = acc[mt][2][di];
                    float Go = acc[mt][3][di];
                    float c2 = sigm(Gf) * cr[ci] + sigm(Gi) * tanhf(Gg);
                    float h2 = sigm(Go) * tanhf(c2);
                    cr[ci] = c2; cn[ci] = c2; hn[ci] = h2;
                    __nv_bfloat16 hh = __float2bfloat16(h2);
                    hb_hi[(size_t)lb * HID + j] = hh;
                    hb_lo[(size_t)lb * HID + j] =
                        __float2bfloat16(h2 - __bfloat162float(hh));
                }

        // ---- release (before the out stores: consumers only need g_hbf) ----
        __threadfence();
        __syncthreads();
        if (tid == 0) atomicAdd(&g_bar[dir][bg][s], 1);

        // ---- off-critical-path: fp32 outputs (+ tails on last step) ----
        #pragma unroll
        for (int mt = 0; mt < 2; mt++)
            #pragma unroll
            for (int rr = 0; rr < 2; rr++)
                #pragma unroll
                for (int jb = 0; jb < 2; jb++) {
                    int lb = wm * 32 + mt * 16 + grp + rr * 8;
                    int gb = bg * 64 + lb;
                    int j = jq * 32 + wn * 8 + tig * 2 + jb;
                    int ci = mt * 4 + rr * 2 + jb;
                    out[(size_t)t * BATCH * OUT_TB_STRIDE + (size_t)gb * OUT_TB_STRIDE
                        + dir * HID + j] = hn[ci];
                    if (s == T_STEPS - 1) {
                        float* tail_h = out + OUT_MAIN + dir * 65536;
                        float* tail_c = tail_h + 32768;
                        tail_h[gb * HID + j] = hn[ci];
                        tail_c[gb * HID + j] = cn[ci];
                    }
                }
    }
}

// ---------------------------------------------------------------------------
extern "C" void kernel_launch(void* const* d_in, const int* in_sizes, int n_in,
                              void* d_out, int out_size)
{
    const float* x     = (const float*)d_in[0];
    const float* h0    = (const float*)d_in[1];
    const float* c0    = (const float*)d_in[2];
    const float* Wih_f = (const float*)d_in[3];
    const float* Whh_f = (const float*)d_in[4];
    const float* bih_f = (const float*)d_in[5];
    const float* bhh_f = (const float*)d_in[6];
    const float* Wih_b = (const float*)d_in[7];
    const float* Whh_b = (const float*)d_in[8];
    const float* bih_b = (const float*)d_in[9];
    const float* bhh_b = (const float*)d_in[10];
    float* out = (float*)d_out;

    static cudaStream_t s_gemm = nullptr;
    static cudaEvent_t ev_fork = nullptr, ev_join = nullptr;
    if (!s_gemm) {
        cudaStreamCreateWithFlags(&s_gemm, cudaStreamNonBlocking);
        cudaEventCreateWithFlags(&ev_fork, cudaEventDisableTiming);
        cudaEventCreateWithFlags(&ev_join, cudaEventDisableTiming);
    }

    cudaFuncSetAttribute(lstm_mma_kernel,
                         cudaFuncAttributeMaxDynamicSharedMemorySize, SMEM_TOTAL);
    cudaFuncSetAttribute(gemm_hmma_kernel,
                         cudaFuncAttributeMaxDynamicSharedMemorySize, GEMM_SMEM);

    // init + splits on the capture stream
    init_misc_kernel<<<256, 256>>>(h0);
    split_w_kernel<<<2048, 256>>>(Wih_f, Wih_b, bih_f, bhh_f, bih_b, bhh_b);
    split_x_kernel<<<8192, 256>>>(x);

    // fork: side stream runs the HMMA xg gemm concurrently
    cudaEventRecord(ev_fork, 0);
    cudaStreamWaitEvent(s_gemm, ev_fork, 0);
    gemm_hmma_kernel<<<dim3(16, 512), 512, GEMM_SMEM, s_gemm>>>();
    cudaEventRecord(ev_join, s_gemm);

    // main stream: persistent HMMA recurrence (consumes xg per-t)
    lstm_mma_kernel<<<32, 256, SMEM_TOTAL>>>(Whh_f, Whh_b, c0, out);

    // join
    cudaStreamWaitEvent(0, ev_join, 0);
}